// round 1
// baseline (speedup 1.0000x reference)
#include <cuda_runtime.h>
#include <cstddef>

// Problem constants (match reference)
#define NROWS 32768
#define DDIM  64
#define RRULE 32
#define EPSF  1e-12f

#define WARPS_PER_BLOCK 8
#define ROWS_PER_WARP   4
#define THREADS (WARPS_PER_BLOCK * 32)
#define NBLOCKS (NROWS / (WARPS_PER_BLOCK * ROWS_PER_WARP))  // 1024
#define PSTRIDE 33   // padded [d][r] stride to kill STS bank conflicts

// Output layout (flattened tuple): y[N] | w[N*R] | Phi[N*R*(D+1)]
#define OFF_W   ((size_t)NROWS)
#define OFF_PHI ((size_t)NROWS + (size_t)NROWS * RRULE)
#define PHI_ROW (RRULE * (DDIM + 1))  // 2080

__global__ __launch_bounds__(THREADS)
void tsk_kernel(const float* __restrict__ Xz,
                const float* __restrict__ C,
                const float* __restrict__ S,
                const float* __restrict__ Th,
                float* __restrict__ out)
{
    __shared__ float c_sh [DDIM * PSTRIDE];
    __shared__ float is_sh[DDIM * PSTRIDE];
    __shared__ float th_sh[DDIM * PSTRIDE];
    __shared__ float tb_sh[RRULE];
    __shared__ float x_sh [WARPS_PER_BLOCK][ROWS_PER_WARP][DDIM];
    __shared__ float ws_sh[WARPS_PER_BLOCK][ROWS_PER_WARP][RRULE];

    const int tid = threadIdx.x;

    // ---- load params into shared, transposed to [d][r] ----
    for (int i = tid; i < RRULE * DDIM; i += THREADS) {
        int r = i / DDIM, d = i % DDIM;
        c_sh [d * PSTRIDE + r] = C[i];
        is_sh[d * PSTRIDE + r] = 1.0f / (S[i] + EPSF);
    }
    for (int i = tid; i < RRULE * (DDIM + 1); i += THREADS) {
        int r = i / (DDIM + 1), k = i % (DDIM + 1);
        if (k == 0) tb_sh[r] = Th[i];
        else        th_sh[(k - 1) * PSTRIDE + r] = Th[i];
    }

    const int warp = tid >> 5;
    const int lane = tid & 31;
    const int gw   = blockIdx.x * WARPS_PER_BLOCK + warp;
    const int row0 = gw * ROWS_PER_WARP;

    // ---- load 4 consecutive rows of x (256 contiguous floats) ----
    {
        const float4* xg = (const float4*)(Xz + (size_t)row0 * DDIM);
        float4* xs = (float4*)(&x_sh[warp][0][0]);
        xs[lane]      = xg[lane];
        xs[lane + 32] = xg[lane + 32];
    }
    __syncthreads();

    // ---- main loop: per-lane rule, 4 rows at once ----
    float acc0 = 0.f, acc1 = 0.f, acc2 = 0.f, acc3 = 0.f;
    const float tb = tb_sh[lane];
    float t0 = tb, t1 = tb, t2 = tb, t3 = tb;

    #pragma unroll 8
    for (int d = 0; d < DDIM; d++) {
        const float c  = c_sh [d * PSTRIDE + lane];
        const float is = is_sh[d * PSTRIDE + lane];
        const float th = th_sh[d * PSTRIDE + lane];
        float x, z;
        x = x_sh[warp][0][d]; z = (x - c) * is; acc0 = fmaf(z, z, acc0); t0 = fmaf(th, x, t0);
        x = x_sh[warp][1][d]; z = (x - c) * is; acc1 = fmaf(z, z, acc1); t1 = fmaf(th, x, t1);
        x = x_sh[warp][2][d]; z = (x - c) * is; acc2 = fmaf(z, z, acc2); t2 = fmaf(th, x, t2);
        x = x_sh[warp][3][d]; z = (x - c) * is; acc3 = fmaf(z, z, acc3); t3 = fmaf(th, x, t3);
    }

    // ---- softmax + w/y outputs, per row ----
    const float accs[4] = {acc0, acc1, acc2, acc3};
    const float ts[4]   = {t0, t1, t2, t3};
    #pragma unroll
    for (int q = 0; q < ROWS_PER_WARP; q++) {
        float lw = -0.5f * accs[q];
        float mx = lw;
        #pragma unroll
        for (int o = 16; o > 0; o >>= 1)
            mx = fmaxf(mx, __shfl_xor_sync(0xFFFFFFFFu, mx, o));
        float e = __expf(lw - mx);
        float s = e;
        #pragma unroll
        for (int o = 16; o > 0; o >>= 1)
            s += __shfl_xor_sync(0xFFFFFFFFu, s, o);
        float w = e / (s + EPSF);
        ws_sh[warp][q][lane] = w;
        out[OFF_W + (size_t)(row0 + q) * RRULE + lane] = w;
        float p = w * ts[q];
        #pragma unroll
        for (int o = 16; o > 0; o >>= 1)
            p += __shfl_xor_sync(0xFFFFFFFFu, p, o);
        if (lane == 0) out[row0 + q] = p;
    }
    __syncwarp();

    // ---- Phi: 4 rows fused per iteration, coalesced streaming stores ----
    float* __restrict__ phi = out + OFF_PHI + (size_t)row0 * PHI_ROW;
    #pragma unroll 1
    for (int j = 0; j < (PHI_ROW + 31) / 32; j++) {   // 65 iterations
        const int idx = j * 32 + lane;                 // 0..2079
        const unsigned r = (unsigned)idx / 65u;
        const int k = idx - (int)r * 65;
        float xv0, xv1, xv2, xv3;
        if (k == 0) { xv0 = xv1 = xv2 = xv3 = 1.0f; }
        else {
            xv0 = x_sh[warp][0][k - 1];
            xv1 = x_sh[warp][1][k - 1];
            xv2 = x_sh[warp][2][k - 1];
            xv3 = x_sh[warp][3][k - 1];
        }
        __stcs(&phi[0 * (size_t)PHI_ROW + idx], ws_sh[warp][0][r] * xv0);
        __stcs(&phi[1 * (size_t)PHI_ROW + idx], ws_sh[warp][1][r] * xv1);
        __stcs(&phi[2 * (size_t)PHI_ROW + idx], ws_sh[warp][2][r] * xv2);
        __stcs(&phi[3 * (size_t)PHI_ROW + idx], ws_sh[warp][3][r] * xv3);
    }
}

extern "C" void kernel_launch(void* const* d_in, const int* in_sizes, int n_in,
                              void* d_out, int out_size)
{
    const float* Xz = (const float*)d_in[0];
    const float* C  = (const float*)d_in[1];
    const float* S  = (const float*)d_in[2];
    const float* Th = (const float*)d_in[3];
    float* out = (float*)d_out;
    (void)in_sizes; (void)n_in; (void)out_size;
    tsk_kernel<<<NBLOCKS, THREADS>>>(Xz, C, S, Th, out);
}